// round 2
// baseline (speedup 1.0000x reference)
#include <cuda_runtime.h>
#include <math.h>
#include <stdint.h>

#define T_TOK 4096
#define D_DIM 1024
#define F_DIM 4096
#define N_EXP 8
#define TOTAL_ROWS (T_TOK * 2)

#define TM 128
#define TN 128
#define TK 16

// ---- scratch (device globals: no allocations allowed) ----
__device__ float g_H[(size_t)TOTAL_ROWS * F_DIM];   // 128 MB intermediate
__device__ int   g_rowmap[TOTAL_ROWS];
__device__ float g_roww[TOTAL_ROWS];
__device__ int   g_counts[N_EXP];
__device__ int   g_offsets[N_EXP];
__device__ int   g_cursor[N_EXP];
__device__ int   g_tope[T_TOK * 2];
__device__ float g_topw[T_TOK * 2];

// ---------------------------------------------------------------------------
// 1. zero d_out (atomic-accumulated later) + reset counts
// ---------------------------------------------------------------------------
__global__ void zero_init_kernel(float* __restrict__ out) {
    int i = blockIdx.x * blockDim.x + threadIdx.x;
    float4 z = make_float4(0.f, 0.f, 0.f, 0.f);
    ((float4*)out)[i] = z;   // grid sized exactly: 4194304/4 float4s
    if (blockIdx.x == 0 && threadIdx.x < N_EXP) g_counts[threadIdx.x] = 0;
}

// ---------------------------------------------------------------------------
// 2. router: one warp per token. logits = x . Wr^T, softmax top-2 renormalized
// ---------------------------------------------------------------------------
__global__ void router_kernel(const float* __restrict__ x,
                              const float* __restrict__ Wr) {
    int gtid = blockIdx.x * blockDim.x + threadIdx.x;
    int t = gtid >> 5;
    int lane = gtid & 31;
    if (t >= T_TOK) return;

    const float* xr = x + (size_t)t * D_DIM;
    float xv[32];
#pragma unroll
    for (int i = 0; i < 32; i++) xv[i] = xr[lane + i * 32];

    float logit[N_EXP];
#pragma unroll
    for (int e = 0; e < N_EXP; e++) {
        const float* w = Wr + (size_t)e * D_DIM;
        float s = 0.f;
#pragma unroll
        for (int i = 0; i < 32; i++) s += xv[i] * w[lane + i * 32];
#pragma unroll
        for (int o = 16; o > 0; o >>= 1) s += __shfl_xor_sync(0xffffffffu, s, o);
        logit[e] = s;
    }

    if (lane == 0) {
        int i0 = 0; float m0 = logit[0];
#pragma unroll
        for (int e = 1; e < N_EXP; e++)
            if (logit[e] > m0) { m0 = logit[e]; i0 = e; }
        int i1 = -1; float m1 = -3.0e38f;
#pragma unroll
        for (int e = 0; e < N_EXP; e++)
            if (e != i0 && logit[e] > m1) { m1 = logit[e]; i1 = e; }
        // top-2 of softmax renormalized == softmax over the 2 logits
        float e1 = expf(m1 - m0);
        float w0 = 1.f / (1.f + e1);
        float w1 = e1 * w0;
        g_tope[2 * t] = i0;     g_topw[2 * t] = w0;
        g_tope[2 * t + 1] = i1; g_topw[2 * t + 1] = w1;
        atomicAdd(&g_counts[i0], 1);
        atomicAdd(&g_counts[i1], 1);
    }
}

// ---------------------------------------------------------------------------
// 3. tiny exclusive scan over 8 experts
// ---------------------------------------------------------------------------
__global__ void scan_kernel() {
    int o = 0;
    for (int e = 0; e < N_EXP; e++) {
        g_offsets[e] = o;
        g_cursor[e] = o;
        o += g_counts[e];
    }
}

// ---------------------------------------------------------------------------
// 4. fill per-expert row lists
// ---------------------------------------------------------------------------
__global__ void fill_kernel() {
    int t = blockIdx.x * blockDim.x + threadIdx.x;
    if (t >= T_TOK) return;
#pragma unroll
    for (int k = 0; k < 2; k++) {
        int e = g_tope[2 * t + k];
        int pos = atomicAdd(&g_cursor[e], 1);
        g_rowmap[pos] = t;
        g_roww[pos] = g_topw[2 * t + k];
    }
}

// ---------------------------------------------------------------------------
// 5. GEMM1: H[row, f] = gelu( sum_d x[tok(row), d] * W1[e, f, d] + b1[e, f] )
//    128x128x16 tile, 256 threads, 8x8 microtile, fp32 FFMA
// ---------------------------------------------------------------------------
__global__ __launch_bounds__(256) void gemm1_kernel(
    const float* __restrict__ x,
    const float* __restrict__ W1,
    const float* __restrict__ b1) {
    int e = blockIdx.z;
    int rows = g_counts[e];
    int m0 = blockIdx.y * TM;
    if (m0 >= rows) return;
    int base = g_offsets[e];
    int n0 = blockIdx.x * TN;

    __shared__ __align__(16) float As[TK][TM + 8];
    __shared__ __align__(16) float Bs[TK][TN + 8];

    int tid = threadIdx.x;
    int tx = tid & 15, ty = tid >> 4;

    // each thread loads 2 float4 of A-tile and 2 float4 of B-tile per k-tile
    int rA0 = tid >> 2,          cA0 = tid & 3;
    int rA1 = (tid + 256) >> 2,  cA1 = (tid + 256) & 3;

    int tok0 = (m0 + rA0 < rows) ? g_rowmap[base + m0 + rA0] : g_rowmap[base];
    int tok1 = (m0 + rA1 < rows) ? g_rowmap[base + m0 + rA1] : g_rowmap[base];
    const float* aptr0 = x + (size_t)tok0 * D_DIM + cA0 * 4;
    const float* aptr1 = x + (size_t)tok1 * D_DIM + cA1 * 4;
    const float* bptr0 = W1 + ((size_t)e * F_DIM + n0 + rA0) * D_DIM + cA0 * 4;
    const float* bptr1 = W1 + ((size_t)e * F_DIM + n0 + rA1) * D_DIM + cA1 * 4;

    float acc[8][8];
#pragma unroll
    for (int i = 0; i < 8; i++)
#pragma unroll
        for (int j = 0; j < 8; j++) acc[i][j] = 0.f;

    for (int kt = 0; kt < D_DIM; kt += TK) {
        float4 av0 = *(const float4*)(aptr0 + kt);
        float4 av1 = *(const float4*)(aptr1 + kt);
        float4 bv0 = *(const float4*)(bptr0 + kt);
        float4 bv1 = *(const float4*)(bptr1 + kt);
        __syncthreads();
        As[cA0 * 4 + 0][rA0] = av0.x; As[cA0 * 4 + 1][rA0] = av0.y;
        As[cA0 * 4 + 2][rA0] = av0.z; As[cA0 * 4 + 3][rA0] = av0.w;
        As[cA1 * 4 + 0][rA1] = av1.x; As[cA1 * 4 + 1][rA1] = av1.y;
        As[cA1 * 4 + 2][rA1] = av1.z; As[cA1 * 4 + 3][rA1] = av1.w;
        Bs[cA0 * 4 + 0][rA0] = bv0.x; Bs[cA0 * 4 + 1][rA0] = bv0.y;
        Bs[cA0 * 4 + 2][rA0] = bv0.z; Bs[cA0 * 4 + 3][rA0] = bv0.w;
        Bs[cA1 * 4 + 0][rA1] = bv1.x; Bs[cA1 * 4 + 1][rA1] = bv1.y;
        Bs[cA1 * 4 + 2][rA1] = bv1.z; Bs[cA1 * 4 + 3][rA1] = bv1.w;
        __syncthreads();
#pragma unroll
        for (int kk = 0; kk < TK; kk++) {
            float4 a0 = *(const float4*)&As[kk][ty * 8];
            float4 a1 = *(const float4*)&As[kk][ty * 8 + 4];
            float4 b0 = *(const float4*)&Bs[kk][tx * 8];
            float4 b1v = *(const float4*)&Bs[kk][tx * 8 + 4];
            float a[8] = {a0.x, a0.y, a0.z, a0.w, a1.x, a1.y, a1.z, a1.w};
            float b[8] = {b0.x, b0.y, b0.z, b0.w, b1v.x, b1v.y, b1v.z, b1v.w};
#pragma unroll
            for (int i = 0; i < 8; i++)
#pragma unroll
                for (int j = 0; j < 8; j++) acc[i][j] += a[i] * b[j];
        }
    }

    const float* b1e = b1 + (size_t)e * F_DIM + n0 + tx * 8;
#pragma unroll
    for (int i = 0; i < 8; i++) {
        int gr = m0 + ty * 8 + i;
        if (gr < rows) {
            float* hp = g_H + (size_t)(base + gr) * F_DIM + n0 + tx * 8;
#pragma unroll
            for (int j = 0; j < 8; j++) {
                float v = acc[i][j] + b1e[j];
                hp[j] = 0.5f * v * (1.0f + erff(v * 0.7071067811865475f));
            }
        }
    }
}

// ---------------------------------------------------------------------------
// 6. GEMM2: Y[row, d] = sum_f H[row, f] * W2[e, d, f] + b2[e, d]
//    out[tok, d] += w_row * Y   (exactly 2 atomic adds per element: deterministic)
// ---------------------------------------------------------------------------
__global__ __launch_bounds__(256) void gemm2_kernel(
    const float* __restrict__ W2,
    const float* __restrict__ b2,
    float* __restrict__ out) {
    int e = blockIdx.z;
    int rows = g_counts[e];
    int m0 = blockIdx.y * TM;
    if (m0 >= rows) return;
    int base = g_offsets[e];
    int n0 = blockIdx.x * TN;  // over D_DIM

    __shared__ __align__(16) float As[TK][TM + 8];
    __shared__ __align__(16) float Bs[TK][TN + 8];

    int tid = threadIdx.x;
    int tx = tid & 15, ty = tid >> 4;

    int rA0 = tid >> 2,          cA0 = tid & 3;
    int rA1 = (tid + 256) >> 2,  cA1 = (tid + 256) & 3;

    int hr0 = (m0 + rA0 < rows) ? (m0 + rA0) : 0;
    int hr1 = (m0 + rA1 < rows) ? (m0 + rA1) : 0;
    const float* aptr0 = g_H + (size_t)(base + hr0) * F_DIM + cA0 * 4;
    const float* aptr1 = g_H + (size_t)(base + hr1) * F_DIM + cA1 * 4;
    const float* bptr0 = W2 + ((size_t)e * D_DIM + n0 + rA0) * F_DIM + cA0 * 4;
    const float* bptr1 = W2 + ((size_t)e * D_DIM + n0 + rA1) * F_DIM + cA1 * 4;

    float acc[8][8];
#pragma unroll
    for (int i = 0; i < 8; i++)
#pragma unroll
        for (int j = 0; j < 8; j++) acc[i][j] = 0.f;

    for (int kt = 0; kt < F_DIM; kt += TK) {
        float4 av0 = *(const float4*)(aptr0 + kt);
        float4 av1 = *(const float4*)(aptr1 + kt);
        float4 bv0 = *(const float4*)(bptr0 + kt);
        float4 bv1 = *(const float4*)(bptr1 + kt);
        __syncthreads();
        As[cA0 * 4 + 0][rA0] = av0.x; As[cA0 * 4 + 1][rA0] = av0.y;
        As[cA0 * 4 + 2][rA0] = av0.z; As[cA0 * 4 + 3][rA0] = av0.w;
        As[cA1 * 4 + 0][rA1] = av1.x; As[cA1 * 4 + 1][rA1] = av1.y;
        As[cA1 * 4 + 2][rA1] = av1.z; As[cA1 * 4 + 3][rA1] = av1.w;
        Bs[cA0 * 4 + 0][rA0] = bv0.x; Bs[cA0 * 4 + 1][rA0] = bv0.y;
        Bs[cA0 * 4 + 2][rA0] = bv0.z; Bs[cA0 * 4 + 3][rA0] = bv0.w;
        Bs[cA1 * 4 + 0][rA1] = bv1.x; Bs[cA1 * 4 + 1][rA1] = bv1.y;
        Bs[cA1 * 4 + 2][rA1] = bv1.z; Bs[cA1 * 4 + 3][rA1] = bv1.w;
        __syncthreads();
#pragma unroll
        for (int kk = 0; kk < TK; kk++) {
            float4 a0 = *(const float4*)&As[kk][ty * 8];
            float4 a1 = *(const float4*)&As[kk][ty * 8 + 4];
            float4 b0 = *(const float4*)&Bs[kk][tx * 8];
            float4 b1v = *(const float4*)&Bs[kk][tx * 8 + 4];
            float a[8] = {a0.x, a0.y, a0.z, a0.w, a1.x, a1.y, a1.z, a1.w};
            float b[8] = {b0.x, b0.y, b0.z, b0.w, b1v.x, b1v.y, b1v.z, b1v.w};
#pragma unroll
            for (int i = 0; i < 8; i++)
#pragma unroll
                for (int j = 0; j < 8; j++) acc[i][j] += a[i] * b[j];
        }
    }

    const float* b2e = b2 + (size_t)e * D_DIM + n0 + tx * 8;
#pragma unroll
    for (int i = 0; i < 8; i++) {
        int gr = m0 + ty * 8 + i;
        if (gr < rows) {
            int tok = g_rowmap[base + gr];
            float w = g_roww[base + gr];
            float* op = out + (size_t)tok * D_DIM + n0 + tx * 8;
#pragma unroll
            for (int j = 0; j < 8; j++) {
                float v = acc[i][j] + b2e[j];
                atomicAdd(&op[j], w * v);
            }
        }
    }
}

// ---------------------------------------------------------------------------
extern "C" void kernel_launch(void* const* d_in, const int* in_sizes, int n_in,
                              void* d_out, int out_size) {
    const float* x  = (const float*)d_in[0];  // [2,2048,1024]
    const float* Wr = (const float*)d_in[1];  // [8,1024]
    const float* W1 = (const float*)d_in[2];  // [8,4096,1024]
    const float* b1 = (const float*)d_in[3];  // [8,4096]
    const float* W2 = (const float*)d_in[4];  // [8,1024,4096]
    const float* b2 = (const float*)d_in[5];  // [8,1024]
    float* out = (float*)d_out;               // [2,2048,1024] fp32

    // 4194304 floats = 1048576 float4
    zero_init_kernel<<<4096, 256>>>(out);
    router_kernel<<<(T_TOK * 32) / 256, 256>>>(x, Wr);
    scan_kernel<<<1, 1>>>();
    fill_kernel<<<T_TOK / 256, 256>>>();
    gemm1_kernel<<<dim3(F_DIM / TN, T_TOK / TM, N_EXP), 256>>>(x, W1, b1);
    gemm2_kernel<<<dim3(D_DIM / TN, T_TOK / TM, N_EXP), 256>>>(W2, b2, out);
}

// round 7
// speedup vs baseline: 1.5530x; 1.5530x over previous
#include <cuda_runtime.h>
#include <cuda_bf16.h>
#include <math.h>
#include <stdint.h>

#define T_TOK 4096
#define D_DIM 1024
#define F_DIM 4096
#define N_EXP 8
#define TOTAL_ROWS (T_TOK * 2)

#define TM 128
#define TN 128
#define BK 32

// smem: 4 planes per stage, 80-byte row stride (32 bf16 + 8 pad)
#define ROWB 80
#define PLANE (128 * ROWB)          // 10240
#define AHI 0
#define ALO PLANE
#define BHI (2 * PLANE)
#define BLO (3 * PLANE)
#define STAGE (4 * PLANE)           // 40960
#define DSMEM (2 * STAGE)           // 81920

// ---- scratch (device globals: no allocations allowed) ----
__device__ uint32_t g_H[(size_t)TOTAL_ROWS * F_DIM];  // packed (hi_bf16 | lo_bf16<<16)
__device__ int   g_rowmap[TOTAL_ROWS];
__device__ float g_roww[TOTAL_ROWS];
__device__ int   g_counts[N_EXP];
__device__ int   g_offsets[N_EXP];
__device__ int   g_cursor[N_EXP];
__device__ int   g_tope[T_TOK * 2];
__device__ float g_topw[T_TOK * 2];

// ---------------- helpers ----------------
__device__ __forceinline__ void mma16816(float* c, uint32_t a0, uint32_t a1,
                                         uint32_t a2, uint32_t a3,
                                         uint32_t b0, uint32_t b1) {
    asm volatile("mma.sync.aligned.m16n8k16.row.col.f32.bf16.bf16.f32 "
                 "{%0,%1,%2,%3}, {%4,%5,%6,%7}, {%8,%9}, {%0,%1,%2,%3};"
                 : "+f"(c[0]), "+f"(c[1]), "+f"(c[2]), "+f"(c[3])
                 : "r"(a0), "r"(a1), "r"(a2), "r"(a3), "r"(b0), "r"(b1));
}

// split fp32x4 -> bf16 hi x4 (uint2) + bf16 lo x4 (uint2)
__device__ __forceinline__ void split4(float4 v, uint2& hi, uint2& lo) {
    __nv_bfloat16 hx = __float2bfloat16_rn(v.x);
    __nv_bfloat16 hy = __float2bfloat16_rn(v.y);
    __nv_bfloat16 hz = __float2bfloat16_rn(v.z);
    __nv_bfloat16 hw = __float2bfloat16_rn(v.w);
    __nv_bfloat16 lx = __float2bfloat16_rn(v.x - __bfloat162float(hx));
    __nv_bfloat16 ly = __float2bfloat16_rn(v.y - __bfloat162float(hy));
    __nv_bfloat16 lz = __float2bfloat16_rn(v.z - __bfloat162float(hz));
    __nv_bfloat16 lw = __float2bfloat16_rn(v.w - __bfloat162float(hw));
    hi.x = (uint32_t)__bfloat16_as_ushort(hx) | ((uint32_t)__bfloat16_as_ushort(hy) << 16);
    hi.y = (uint32_t)__bfloat16_as_ushort(hz) | ((uint32_t)__bfloat16_as_ushort(hw) << 16);
    lo.x = (uint32_t)__bfloat16_as_ushort(lx) | ((uint32_t)__bfloat16_as_ushort(ly) << 16);
    lo.y = (uint32_t)__bfloat16_as_ushort(lz) | ((uint32_t)__bfloat16_as_ushort(lw) << 16);
}

// compute one BK=32 stage from buffer bufp into acc
__device__ __forceinline__ void compute_stage(const char* bufp, int wm, int wn,
                                              int g, int q2, float acc[4][4][4]) {
#pragma unroll
    for (int ks = 0; ks < 2; ks++) {
        // k-slice byte offset: ks*16 bf16 = ks*32 bytes; lane quad q2 -> k elem 2*q2 -> byte 4*q2
        int kb = ks * 32 + 4 * q2;
        uint32_t bh[4][2], bl[4][2];
#pragma unroll
        for (int nj = 0; nj < 4; nj++) {
            int nrow = wn * 32 + nj * 8 + g;
            const char* pb = bufp + nrow * ROWB + kb;
            bh[nj][0] = *(const uint32_t*)(pb + BHI);
            bh[nj][1] = *(const uint32_t*)(pb + BHI + 16);
            bl[nj][0] = *(const uint32_t*)(pb + BLO);
            bl[nj][1] = *(const uint32_t*)(pb + BLO + 16);
        }
#pragma unroll
        for (int mi = 0; mi < 4; mi++) {
            int mrow = wm * 64 + mi * 16 + g;
            const char* pa = bufp + mrow * ROWB + kb;
            uint32_t ah0 = *(const uint32_t*)(pa + AHI);
            uint32_t ah1 = *(const uint32_t*)(pa + AHI + 8 * ROWB);
            uint32_t ah2 = *(const uint32_t*)(pa + AHI + 16);
            uint32_t ah3 = *(const uint32_t*)(pa + AHI + 8 * ROWB + 16);
            uint32_t al0 = *(const uint32_t*)(pa + ALO);
            uint32_t al1 = *(const uint32_t*)(pa + ALO + 8 * ROWB);
            uint32_t al2 = *(const uint32_t*)(pa + ALO + 16);
            uint32_t al3 = *(const uint32_t*)(pa + ALO + 8 * ROWB + 16);
#pragma unroll
            for (int nj = 0; nj < 4; nj++) {
                mma16816(acc[mi][nj], ah0, ah1, ah2, ah3, bh[nj][0], bh[nj][1]);
                mma16816(acc[mi][nj], al0, al1, al2, al3, bh[nj][0], bh[nj][1]);
                mma16816(acc[mi][nj], ah0, ah1, ah2, ah3, bl[nj][0], bl[nj][1]);
            }
        }
    }
}

// ---------------------------------------------------------------------------
__global__ void zero_init_kernel(float* __restrict__ out) {
    int i = blockIdx.x * blockDim.x + threadIdx.x;
    ((float4*)out)[i] = make_float4(0.f, 0.f, 0.f, 0.f);
    if (blockIdx.x == 0 && threadIdx.x < N_EXP) g_counts[threadIdx.x] = 0;
}

__global__ void router_kernel(const float* __restrict__ x, const float* __restrict__ Wr) {
    int gtid = blockIdx.x * blockDim.x + threadIdx.x;
    int t = gtid >> 5, lane = gtid & 31;
    if (t >= T_TOK) return;
    const float* xr = x + (size_t)t * D_DIM;
    float xv[32];
#pragma unroll
    for (int i = 0; i < 32; i++) xv[i] = xr[lane + i * 32];
    float logit[N_EXP];
#pragma unroll
    for (int e = 0; e < N_EXP; e++) {
        const float* w = Wr + (size_t)e * D_DIM;
        float s = 0.f;
#pragma unroll
        for (int i = 0; i < 32; i++) s += xv[i] * w[lane + i * 32];
#pragma unroll
        for (int o = 16; o > 0; o >>= 1) s += __shfl_xor_sync(0xffffffffu, s, o);
        logit[e] = s;
    }
    if (lane == 0) {
        int i0 = 0; float m0v = logit[0];
#pragma unroll
        for (int e = 1; e < N_EXP; e++) if (logit[e] > m0v) { m0v = logit[e]; i0 = e; }
        int i1 = -1; float m1v = -3.0e38f;
#pragma unroll
        for (int e = 0; e < N_EXP; e++) if (e != i0 && logit[e] > m1v) { m1v = logit[e]; i1 = e; }
        float e1 = expf(m1v - m0v);
        float w0 = 1.f / (1.f + e1);
        float w1 = e1 * w0;
        g_tope[2 * t] = i0;     g_topw[2 * t] = w0;
        g_tope[2 * t + 1] = i1; g_topw[2 * t + 1] = w1;
        atomicAdd(&g_counts[i0], 1);
        atomicAdd(&g_counts[i1], 1);
    }
}

__global__ void scan_kernel() {
    int o = 0;
    for (int e = 0; e < N_EXP; e++) { g_offsets[e] = o; g_cursor[e] = o; o += g_counts[e]; }
}

__global__ void fill_kernel() {
    int t = blockIdx.x * blockDim.x + threadIdx.x;
    if (t >= T_TOK) return;
#pragma unroll
    for (int k = 0; k < 2; k++) {
        int e = g_tope[2 * t + k];
        int pos = atomicAdd(&g_cursor[e], 1);
        g_rowmap[pos] = t;
        g_roww[pos] = g_topw[2 * t + k];
    }
}

// ---------------------------------------------------------------------------
// GEMM1: H = gelu( gather(x) @ W1^T + b1 ); H packed (hi|lo) bf16 per uint32
// ---------------------------------------------------------------------------
__global__ __launch_bounds__(256) void gemm1_mma(
    const float* __restrict__ x, const float* __restrict__ W1, const float* __restrict__ b1) {
    int e = blockIdx.z;
    int rows = g_counts[e];
    int m0 = blockIdx.y * TM;
    if (m0 >= rows) return;
    int base = g_offsets[e];
    int n0 = blockIdx.x * TN;

    extern __shared__ char smem[];
    int tid = threadIdx.x;
    int wid = tid >> 5, lane = tid & 31;
    int wm = wid & 1, wn = wid >> 1;
    int g = lane >> 2, q2 = lane & 3;

    // producers: 2 threads per row, 16 floats each
    int r = tid >> 1, h = tid & 1;
    int ar = m0 + r; if (ar >= rows) ar = rows - 1;
    const float* ap = x + (size_t)g_rowmap[base + ar] * D_DIM + h * 16;
    const float* bp = W1 + ((size_t)e * F_DIM + n0 + r) * D_DIM + h * 16;
    uint32_t soff = r * ROWB + h * 32;  // byte offset of first of 16 bf16

    float acc[4][4][4];
#pragma unroll
    for (int i = 0; i < 4; i++)
#pragma unroll
        for (int j = 0; j < 4; j++)
#pragma unroll
            for (int k = 0; k < 4; k++) acc[i][j][k] = 0.f;

    const int NST = D_DIM / BK;  // 32
    float4 av[4], bv[4];
#pragma unroll
    for (int i = 0; i < 4; i++) { av[i] = ((const float4*)ap)[i]; bv[i] = ((const float4*)bp)[i]; }
    {
        char* bufp = smem;
#pragma unroll
        for (int i = 0; i < 4; i++) {
            uint2 hi, lo;
            split4(av[i], hi, lo);
            *(uint2*)(bufp + AHI + soff + i * 8) = hi;
            *(uint2*)(bufp + ALO + soff + i * 8) = lo;
            split4(bv[i], hi, lo);
            *(uint2*)(bufp + BHI + soff + i * 8) = hi;
            *(uint2*)(bufp + BLO + soff + i * 8) = lo;
        }
    }
    __syncthreads();

    for (int kt = 0; kt < NST; kt++) {
        bool more = (kt + 1) < NST;
        if (more) {
            const float* ap2 = ap + (kt + 1) * BK;
            const float* bp2 = bp + (kt + 1) * BK;
#pragma unroll
            for (int i = 0; i < 4; i++) { av[i] = ((const float4*)ap2)[i]; bv[i] = ((const float4*)bp2)[i]; }
        }
        compute_stage(smem + (kt & 1) * STAGE, wm, wn, g, q2, acc);
        if (more) {
            char* bufp = smem + ((kt + 1) & 1) * STAGE;
#pragma unroll
            for (int i = 0; i < 4; i++) {
                uint2 hi, lo;
                split4(av[i], hi, lo);
                *(uint2*)(bufp + AHI + soff + i * 8) = hi;
                *(uint2*)(bufp + ALO + soff + i * 8) = lo;
                split4(bv[i], hi, lo);
                *(uint2*)(bufp + BHI + soff + i * 8) = hi;
                *(uint2*)(bufp + BLO + soff + i * 8) = lo;
            }
        }
        __syncthreads();
    }

    // epilogue: bias + gelu, pack hi/lo into one uint32
    const float* bcol = b1 + (size_t)e * F_DIM + n0 + wn * 32;
#pragma unroll
    for (int mi = 0; mi < 4; mi++) {
#pragma unroll
        for (int half = 0; half < 2; half++) {
            int mrow = wm * 64 + mi * 16 + g + half * 8;
            int gr = m0 + mrow;
            if (gr < rows) {
                uint32_t* hrow = g_H + (size_t)(base + gr) * F_DIM + n0 + wn * 32;
#pragma unroll
                for (int nj = 0; nj < 4; nj++) {
                    int n = nj * 8 + q2 * 2;
                    float v0 = acc[mi][nj][half * 2 + 0] + bcol[n];
                    float v1 = acc[mi][nj][half * 2 + 1] + bcol[n + 1];
                    float g0 = 0.5f * v0 * (1.0f + erff(v0 * 0.7071067811865475f));
                    float g1 = 0.5f * v1 * (1.0f + erff(v1 * 0.7071067811865475f));
                    __nv_bfloat16 h0 = __float2bfloat16_rn(g0);
                    __nv_bfloat16 h1 = __float2bfloat16_rn(g1);
                    __nv_bfloat16 l0 = __float2bfloat16_rn(g0 - __bfloat162float(h0));
                    __nv_bfloat16 l1 = __float2bfloat16_rn(g1 - __bfloat162float(h1));
                    uint2 w;
                    w.x = (uint32_t)__bfloat16_as_ushort(h0) | ((uint32_t)__bfloat16_as_ushort(l0) << 16);
                    w.y = (uint32_t)__bfloat16_as_ushort(h1) | ((uint32_t)__bfloat16_as_ushort(l1) << 16);
                    *(uint2*)(hrow + n) = w;
                }
            }
        }
    }
}

// ---------------------------------------------------------------------------
// GEMM2: Y = H @ W2^T + b2; out[tok] += w * Y (2-way atomic: deterministic)
// ---------------------------------------------------------------------------
__global__ __launch_bounds__(256) void gemm2_mma(
    const float* __restrict__ W2, const float* __restrict__ b2, float* __restrict__ out) {
    int e = blockIdx.z;
    int rows = g_counts[e];
    int m0 = blockIdx.y * TM;
    if (m0 >= rows) return;
    int base = g_offsets[e];
    int n0 = blockIdx.x * TN;   // over D_DIM

    extern __shared__ char smem[];
    int tid = threadIdx.x;
    int wid = tid >> 5, lane = tid & 31;
    int wm = wid & 1, wn = wid >> 1;
    int g = lane >> 2, q2 = lane & 3;

    int r = tid >> 1, h = tid & 1;
    int ar = m0 + r; if (ar >= rows) ar = rows - 1;
    const uint32_t* ap = g_H + (size_t)(base + ar) * F_DIM + h * 16;
    const float* bp = W2 + ((size_t)e * D_DIM + n0 + r) * F_DIM + h * 16;
    uint32_t soff = r * ROWB + h * 32;

    float acc[4][4][4];
#pragma unroll
    for (int i = 0; i < 4; i++)
#pragma unroll
        for (int j = 0; j < 4; j++)
#pragma unroll
            for (int k = 0; k < 4; k++) acc[i][j][k] = 0.f;

    const int NST = F_DIM / BK;  // 128
    uint4 av[4]; float4 bv[4];
#pragma unroll
    for (int i = 0; i < 4; i++) { av[i] = ((const uint4*)ap)[i]; bv[i] = ((const float4*)bp)[i]; }
    {
        char* bufp = smem;
#pragma unroll
        for (int i = 0; i < 4; i++) {
            uint2 hi, lo;
            hi.x = __byte_perm(av[i].x, av[i].y, 0x5410);
            hi.y = __byte_perm(av[i].z, av[i].w, 0x5410);
            lo.x = __byte_perm(av[i].x, av[i].y, 0x7632);
            lo.y = __byte_perm(av[i].z, av[i].w, 0x7632);
            *(uint2*)(bufp + AHI + soff + i * 8) = hi;
            *(uint2*)(bufp + ALO + soff + i * 8) = lo;
            split4(bv[i], hi, lo);
            *(uint2*)(bufp + BHI + soff + i * 8) = hi;
            *(uint2*)(bufp + BLO + soff + i * 8) = lo;
        }
    }
    __syncthreads();

    for (int kt = 0; kt < NST; kt++) {
        bool more = (kt + 1) < NST;
        if (more) {
            const uint32_t* ap2 = ap + (kt + 1) * BK;
            const float* bp2 = bp + (kt + 1) * BK;
#pragma unroll
            for (int i = 0; i < 4; i++) { av[i] = ((const uint4*)ap2)[i]; bv[i] = ((const float4*)bp2)[i]; }
        }
        compute_stage(smem + (kt & 1) * STAGE, wm, wn, g, q2, acc);
        if (more) {
            char* bufp = smem + ((kt + 1) & 1) * STAGE;
#pragma unroll
            for (int i = 0; i < 4; i++) {
                uint2 hi, lo;
                hi.x = __byte_perm(av[i].x, av[i].y, 0x5410);
                hi.y = __byte_perm(av[i].z, av[i].w, 0x5410);
                lo.x = __byte_perm(av[i].x, av[i].y, 0x7632);
                lo.y = __byte_perm(av[i].z, av[i].w, 0x7632);
                *(uint2*)(bufp + AHI + soff + i * 8) = hi;
                *(uint2*)(bufp + ALO + soff + i * 8) = lo;
                split4(bv[i], hi, lo);
                *(uint2*)(bufp + BHI + soff + i * 8) = hi;
                *(uint2*)(bufp + BLO + soff + i * 8) = lo;
            }
        }
        __syncthreads();
    }

    const float* bcol = b2 + (size_t)e * D_DIM + n0 + wn * 32;
#pragma unroll
    for (int mi = 0; mi < 4; mi++) {
#pragma unroll
        for (int half = 0; half < 2; half++) {
            int mrow = wm * 64 + mi * 16 + g + half * 8;
            int gr = m0 + mrow;
            if (gr < rows) {
                int tok = g_rowmap[base + gr];
                float w = g_roww[base + gr];
                float* op = out + (size_t)tok * D_DIM + n0 + wn * 32;
#pragma unroll
                for (int nj = 0; nj < 4; nj++) {
                    int n = nj * 8 + q2 * 2;
                    float v0 = acc[mi][nj][half * 2 + 0] + bcol[n];
                    float v1 = acc[mi][nj][half * 2 + 1] + bcol[n + 1];
                    atomicAdd(&op[n], w * v0);
                    atomicAdd(&op[n + 1], w * v1);
                }
            }
        }
    }
}

// ---------------------------------------------------------------------------
extern "C" void kernel_launch(void* const* d_in, const int* in_sizes, int n_in,
                              void* d_out, int out_size) {
    const float* x  = (const float*)d_in[0];
    const float* Wr = (const float*)d_in[1];
    const float* W1 = (const float*)d_in[2];
    const float* b1 = (const float*)d_in[3];
    const float* W2 = (const float*)d_in[4];
    const float* b2 = (const float*)d_in[5];
    float* out = (float*)d_out;

    cudaFuncSetAttribute(gemm1_mma, cudaFuncAttributeMaxDynamicSharedMemorySize, DSMEM);
    cudaFuncSetAttribute(gemm2_mma, cudaFuncAttributeMaxDynamicSharedMemorySize, DSMEM);

    zero_init_kernel<<<4096, 256>>>(out);
    router_kernel<<<(T_TOK * 32) / 256, 256>>>(x, Wr);
    scan_kernel<<<1, 1>>>();
    fill_kernel<<<T_TOK / 256, 256>>>();
    gemm1_mma<<<dim3(F_DIM / TN, T_TOK / TM, N_EXP), 256, DSMEM>>>(x, W1, b1);
    gemm2_mma<<<dim3(D_DIM / TN, T_TOK / TM, N_EXP), 256, DSMEM>>>(W2, b2, out);
}

// round 9
// speedup vs baseline: 3.1758x; 2.0450x over previous
#include <cuda_runtime.h>
#include <cuda_fp16.h>
#include <math.h>
#include <stdint.h>

#define T_TOK 4096
#define D_DIM 1024
#define F_DIM 4096
#define N_EXP 8
#define TOTAL_ROWS (T_TOK * 2)

#define TM 128
#define TN 128
#define BK 32

// smem: 2 fp16 planes per stage, 80-byte row stride (32 half = 64B data + 16B pad)
// bank check: word = row*20 + q2 ; row*20 mod 32 = {0,20,8,28,16,4,24,12} -> spaced 4 -> +q2 all distinct
#define ROWB 80
#define APL 0
#define BPL (128 * ROWB)            // 10240
#define STAGE (2 * 128 * ROWB)      // 20480
#define DSMEM (2 * STAGE)           // 40960

// ---- scratch (device globals: no allocations allowed) ----
__device__ __half g_Hh[(size_t)TOTAL_ROWS * F_DIM];          // 64MB fp16 intermediate
__device__ __half g_W1h[(size_t)N_EXP * F_DIM * D_DIM];      // 64MB
__device__ __half g_W2h[(size_t)N_EXP * D_DIM * F_DIM];      // 64MB
__device__ __half g_xh[(size_t)T_TOK * D_DIM];               // 8MB
__device__ int   g_rowmap[TOTAL_ROWS];
__device__ float g_roww[TOTAL_ROWS];
__device__ int   g_counts[N_EXP];
__device__ int   g_offsets[N_EXP];
__device__ int   g_cursor[N_EXP];
__device__ int   g_tope[T_TOK * 2];
__device__ float g_topw[T_TOK * 2];

// ---------------- helpers ----------------
__device__ __forceinline__ void mma16816(float* c, uint32_t a0, uint32_t a1,
                                         uint32_t a2, uint32_t a3,
                                         uint32_t b0, uint32_t b1) {
    asm volatile("mma.sync.aligned.m16n8k16.row.col.f32.f16.f16.f32 "
                 "{%0,%1,%2,%3}, {%4,%5,%6,%7}, {%8,%9}, {%0,%1,%2,%3};"
                 : "+f"(c[0]), "+f"(c[1]), "+f"(c[2]), "+f"(c[3])
                 : "r"(a0), "r"(a1), "r"(a2), "r"(a3), "r"(b0), "r"(b1));
}

// compute one BK=32 stage: A plane at bufp+APL, B plane at bufp+BPL
__device__ __forceinline__ void compute_stage(const char* bufp, int wm, int wn,
                                              int g, int q2, float acc[4][4][4]) {
#pragma unroll
    for (int ks = 0; ks < 2; ks++) {
        int kb = ks * 32 + 4 * q2;   // k-slice bytes: ks*16 halves = 32B; quad q2 -> elem 2q2 -> byte 4q2
        uint32_t bf[4][2];
#pragma unroll
        for (int nj = 0; nj < 4; nj++) {
            const char* pb = bufp + BPL + (wn * 32 + nj * 8 + g) * ROWB + kb;
            bf[nj][0] = *(const uint32_t*)(pb);
            bf[nj][1] = *(const uint32_t*)(pb + 16);
        }
#pragma unroll
        for (int mi = 0; mi < 4; mi++) {
            const char* pa = bufp + APL + (wm * 64 + mi * 16 + g) * ROWB + kb;
            uint32_t a0 = *(const uint32_t*)(pa);
            uint32_t a1 = *(const uint32_t*)(pa + 8 * ROWB);
            uint32_t a2 = *(const uint32_t*)(pa + 16);
            uint32_t a3 = *(const uint32_t*)(pa + 8 * ROWB + 16);
#pragma unroll
            for (int nj = 0; nj < 4; nj++)
                mma16816(acc[mi][nj], a0, a1, a2, a3, bf[nj][0], bf[nj][1]);
        }
    }
}

// ---------------------------------------------------------------------------
__global__ void zero_init_kernel(float* __restrict__ out) {
    int i = blockIdx.x * blockDim.x + threadIdx.x;
    ((float4*)out)[i] = make_float4(0.f, 0.f, 0.f, 0.f);
    if (blockIdx.x == 0 && threadIdx.x < N_EXP) g_counts[threadIdx.x] = 0;
}

// fp32 -> fp16 bulk convert (4 elems/thread)
__global__ void f2h_kernel(const float* __restrict__ s, __half* __restrict__ d) {
    int i = blockIdx.x * blockDim.x + threadIdx.x;
    float4 v = ((const float4*)s)[i];
    __half2* dp = (__half2*)d;
    dp[2 * i] = __floats2half2_rn(v.x, v.y);
    dp[2 * i + 1] = __floats2half2_rn(v.z, v.w);
}

__global__ void router_kernel(const float* __restrict__ x, const float* __restrict__ Wr) {
    int gtid = blockIdx.x * blockDim.x + threadIdx.x;
    int t = gtid >> 5, lane = gtid & 31;
    if (t >= T_TOK) return;
    const float* xr = x + (size_t)t * D_DIM;
    float xv[32];
#pragma unroll
    for (int i = 0; i < 32; i++) xv[i] = xr[lane + i * 32];
    float logit[N_EXP];
#pragma unroll
    for (int e = 0; e < N_EXP; e++) {
        const float* w = Wr + (size_t)e * D_DIM;
        float s = 0.f;
#pragma unroll
        for (int i = 0; i < 32; i++) s += xv[i] * w[lane + i * 32];
#pragma unroll
        for (int o = 16; o > 0; o >>= 1) s += __shfl_xor_sync(0xffffffffu, s, o);
        logit[e] = s;
    }
    if (lane == 0) {
        int i0 = 0; float m0v = logit[0];
#pragma unroll
        for (int e = 1; e < N_EXP; e++) if (logit[e] > m0v) { m0v = logit[e]; i0 = e; }
        int i1 = -1; float m1v = -3.0e38f;
#pragma unroll
        for (int e = 0; e < N_EXP; e++) if (e != i0 && logit[e] > m1v) { m1v = logit[e]; i1 = e; }
        float e1 = expf(m1v - m0v);
        float w0 = 1.f / (1.f + e1);
        float w1 = e1 * w0;
        g_tope[2 * t] = i0;     g_topw[2 * t] = w0;
        g_tope[2 * t + 1] = i1; g_topw[2 * t + 1] = w1;
        atomicAdd(&g_counts[i0], 1);
        atomicAdd(&g_counts[i1], 1);
    }
}

__global__ void scan_kernel() {
    int o = 0;
    for (int e = 0; e < N_EXP; e++) { g_offsets[e] = o; g_cursor[e] = o; o += g_counts[e]; }
}

__global__ void fill_kernel() {
    int t = blockIdx.x * blockDim.x + threadIdx.x;
    if (t >= T_TOK) return;
#pragma unroll
    for (int k = 0; k < 2; k++) {
        int e = g_tope[2 * t + k];
        int pos = atomicAdd(&g_cursor[e], 1);
        g_rowmap[pos] = t;
        g_roww[pos] = g_topw[2 * t + k];
    }
}

// ---------------------------------------------------------------------------
// GEMM1: H = gelu( gather(xh) @ W1h^T + b1 ), fp16 MMA, fp32 accum, H -> fp16
// producers: threads 0-127 own A row (tid), 128-255 own B row (tid-128);
// each loads 64 contiguous bytes (32 halves) per stage: 4 LDG.128 + 4 STS.128
// ---------------------------------------------------------------------------
__global__ __launch_bounds__(256) void gemm1_mma(
    const float* __restrict__ b1) {
    int e = blockIdx.z;
    int rows = g_counts[e];
    int m0 = blockIdx.y * TM;
    if (m0 >= rows) return;
    int base = g_offsets[e];
    int n0 = blockIdx.x * TN;

    extern __shared__ char smem[];
    int tid = threadIdx.x;
    int wid = tid >> 5, lane = tid & 31;
    int wm = wid & 1, wn = wid >> 1;
    int g = lane >> 2, q2 = lane & 3;

    int pr = tid & 127;
    bool isB = tid >= 128;
    int ar = m0 + pr; if (ar >= rows) ar = rows - 1;
    const __half* gp = isB ? (g_W1h + ((size_t)e * F_DIM + n0 + pr) * D_DIM)
                           : (g_xh + (size_t)g_rowmap[base + ar] * D_DIM);
    uint32_t soff = (isB ? BPL : APL) + pr * ROWB;

    float acc[4][4][4];
#pragma unroll
    for (int i = 0; i < 4; i++)
#pragma unroll
        for (int j = 0; j < 4; j++)
#pragma unroll
            for (int k = 0; k < 4; k++) acc[i][j][k] = 0.f;

    const int NST = D_DIM / BK;  // 32
    uint4 v[4];
#pragma unroll
    for (int i = 0; i < 4; i++) v[i] = ((const uint4*)gp)[i];
    {
        char* bufp = smem;
#pragma unroll
        for (int i = 0; i < 4; i++) *(uint4*)(bufp + soff + 16 * i) = v[i];
    }
    __syncthreads();

    for (int kt = 0; kt < NST; kt++) {
        bool more = (kt + 1) < NST;
        if (more) {
            const uint4* src = (const uint4*)(gp + (kt + 1) * BK);
#pragma unroll
            for (int i = 0; i < 4; i++) v[i] = src[i];
        }
        compute_stage(smem + (kt & 1) * STAGE, wm, wn, g, q2, acc);
        if (more) {
            char* bufp = smem + ((kt + 1) & 1) * STAGE;
#pragma unroll
            for (int i = 0; i < 4; i++) *(uint4*)(bufp + soff + 16 * i) = v[i];
        }
        __syncthreads();
    }

    // epilogue: bias + gelu -> fp16 H
    const float* bcol = b1 + (size_t)e * F_DIM + n0 + wn * 32;
#pragma unroll
    for (int mi = 0; mi < 4; mi++) {
#pragma unroll
        for (int half_ = 0; half_ < 2; half_++) {
            int gr = m0 + wm * 64 + mi * 16 + g + half_ * 8;
            if (gr < rows) {
                __half* hrow = g_Hh + (size_t)(base + gr) * F_DIM + n0 + wn * 32;
#pragma unroll
                for (int nj = 0; nj < 4; nj++) {
                    int n = nj * 8 + q2 * 2;
                    float v0 = acc[mi][nj][half_ * 2 + 0] + bcol[n];
                    float v1 = acc[mi][nj][half_ * 2 + 1] + bcol[n + 1];
                    float g0 = 0.5f * v0 * (1.0f + erff(v0 * 0.7071067811865475f));
                    float g1 = 0.5f * v1 * (1.0f + erff(v1 * 0.7071067811865475f));
                    *(__half2*)(hrow + n) = __floats2half2_rn(g0, g1);
                }
            }
        }
    }
}

// ---------------------------------------------------------------------------
// GEMM2: Y = Hh @ W2h^T + b2; out[tok] += w * Y (2-way atomic: deterministic)
// ---------------------------------------------------------------------------
__global__ __launch_bounds__(256) void gemm2_mma(
    const float* __restrict__ b2, float* __restrict__ out) {
    int e = blockIdx.z;
    int rows = g_counts[e];
    int m0 = blockIdx.y * TM;
    if (m0 >= rows) return;
    int base = g_offsets[e];
    int n0 = blockIdx.x * TN;   // over D_DIM

    extern __shared__ char smem[];
    int tid = threadIdx.x;
    int wid = tid >> 5, lane = tid & 31;
    int wm = wid & 1, wn = wid >> 1;
    int g = lane >> 2, q2 = lane & 3;

    int pr = tid & 127;
    bool isB = tid >= 128;
    int ar = m0 + pr; if (ar >= rows) ar = rows - 1;
    const __half* gp = isB ? (g_W2h + ((size_t)e * D_DIM + n0 + pr) * F_DIM)
                           : (g_Hh + (size_t)(base + ar) * F_DIM);
    uint32_t soff = (isB ? BPL : APL) + pr * ROWB;

    float acc[4][4][4];
#pragma unroll
    for (int i = 0; i < 4; i++)
#pragma unroll
        for (int j = 0; j < 4; j++)
#pragma unroll
            for (int k = 0; k < 4; k++) acc[i][j][k] = 0.f;

    const int NST = F_DIM / BK;  // 128
    uint4 v[4];
#pragma unroll
    for (int i = 0; i < 4; i++) v[i] = ((const uint4*)gp)[i];
    {
        char* bufp = smem;
#pragma unroll
        for (int i = 0; i < 4; i++) *(uint4*)(bufp + soff + 16 * i) = v[i];
    }
    __syncthreads();

    for (int kt = 0; kt < NST; kt++) {
        bool more = (kt + 1) < NST;
        if (more) {
            const uint4* src = (const uint4*)(gp + (kt + 1) * BK);
#pragma unroll
            for (int i = 0; i < 4; i++) v[i] = src[i];
        }
        compute_stage(smem + (kt & 1) * STAGE, wm, wn, g, q2, acc);
        if (more) {
            char* bufp = smem + ((kt + 1) & 1) * STAGE;
#pragma unroll
            for (int i = 0; i < 4; i++) *(uint4*)(bufp + soff + 16 * i) = v[i];
        }
        __syncthreads();
    }

    const float* bcol = b2 + (size_t)e * D_DIM + n0 + wn * 32;
#pragma unroll
    for (int mi = 0; mi < 4; mi++) {
#pragma unroll
        for (int half_ = 0; half_ < 2; half_++) {
            int gr = m0 + wm * 64 + mi * 16 + g + half_ * 8;
            if (gr < rows) {
                int tok = g_rowmap[base + gr];
                float w = g_roww[base + gr];
                float* op = out + (size_t)tok * D_DIM + n0 + wn * 32;
#pragma unroll
                for (int nj = 0; nj < 4; nj++) {
                    int n = nj * 8 + q2 * 2;
                    float v0 = acc[mi][nj][half_ * 2 + 0] + bcol[n];
                    float v1 = acc[mi][nj][half_ * 2 + 1] + bcol[n + 1];
                    atomicAdd(&op[n], w * v0);
                    atomicAdd(&op[n + 1], w * v1);
                }
            }
        }
    }
}

// ---------------------------------------------------------------------------
extern "C" void kernel_launch(void* const* d_in, const int* in_sizes, int n_in,
                              void* d_out, int out_size) {
    const float* x  = (const float*)d_in[0];
    const float* Wr = (const float*)d_in[1];
    const float* W1 = (const float*)d_in[2];
    const float* b1 = (const float*)d_in[3];
    const float* W2 = (const float*)d_in[4];
    const float* b2 = (const float*)d_in[5];
    float* out = (float*)d_out;

    cudaFuncSetAttribute(gemm1_mma, cudaFuncAttributeMaxDynamicSharedMemorySize, DSMEM);
    cudaFuncSetAttribute(gemm2_mma, cudaFuncAttributeMaxDynamicSharedMemorySize, DSMEM);

    __half *W1h, *W2h, *xh;
    cudaGetSymbolAddress((void**)&W1h, g_W1h);
    cudaGetSymbolAddress((void**)&W2h, g_W2h);
    cudaGetSymbolAddress((void**)&xh, g_xh);

    zero_init_kernel<<<4096, 256>>>(out);
    f2h_kernel<<<(T_TOK * D_DIM / 4) / 256, 256>>>(x, xh);                 // 4096 blocks
    f2h_kernel<<<((size_t)N_EXP * F_DIM * D_DIM / 4) / 256, 256>>>(W1, W1h);
    f2h_kernel<<<((size_t)N_EXP * D_DIM * F_DIM / 4) / 256, 256>>>(W2, W2h);
    router_kernel<<<(T_TOK * 32) / 256, 256>>>(x, Wr);
    scan_kernel<<<1, 1>>>();
    fill_kernel<<<T_TOK / 256, 256>>>();
    gemm1_mma<<<dim3(F_DIM / TN, T_TOK / TM, N_EXP), 256, DSMEM>>>(b1);
    gemm2_mma<<<dim3(D_DIM / TN, T_TOK / TM, N_EXP), 256, DSMEM>>>(b2, out);
}

// round 10
// speedup vs baseline: 3.7094x; 1.1680x over previous
#include <cuda_runtime.h>
#include <cuda_fp16.h>
#include <math.h>
#include <stdint.h>

#define T_TOK 4096
#define D_DIM 1024
#define F_DIM 4096
#define N_EXP 8
#define TOTAL_ROWS (T_TOK * 2)

#define TM 128
#define TN 128
#define BK 32

// smem: 2 fp16 planes per stage, 80-byte row stride (64B data + 16B pad)
#define ROWB 80
#define APL 0
#define BPL (128 * ROWB)            // 10240
#define STAGE (2 * 128 * ROWB)      // 20480
#define NBUF 3
#define DSMEM (NBUF * STAGE)        // 61440

// ---- scratch (device globals: no allocations allowed) ----
__device__ __half g_Hh[(size_t)TOTAL_ROWS * F_DIM];
__device__ __half g_W1h[(size_t)N_EXP * F_DIM * D_DIM];
__device__ __half g_W2h[(size_t)N_EXP * D_DIM * F_DIM];
__device__ __half g_xh[(size_t)T_TOK * D_DIM];
__device__ int   g_rowmap[TOTAL_ROWS];
__device__ float g_roww[TOTAL_ROWS];
__device__ int   g_counts[N_EXP];
__device__ int   g_offsets[N_EXP];
__device__ int   g_cursor[N_EXP];
__device__ int   g_tope[T_TOK * 2];
__device__ float g_topw[T_TOK * 2];

// ---------------- PTX helpers ----------------
__device__ __forceinline__ uint32_t smem_u32(const void* p) {
    uint32_t a;
    asm("{ .reg .u64 t; cvta.to.shared.u64 t, %1; cvt.u32.u64 %0, t; }" : "=r"(a) : "l"(p));
    return a;
}
__device__ __forceinline__ void cp16(uint32_t dst, const void* src) {
    asm volatile("cp.async.cg.shared.global [%0], [%1], 16;" :: "r"(dst), "l"(src));
}
#define CP_COMMIT() asm volatile("cp.async.commit_group;" ::: "memory")
#define CP_WAIT(n)  asm volatile("cp.async.wait_group %0;" :: "n"(n) : "memory")
__device__ __forceinline__ void ldsm4(uint32_t& r0, uint32_t& r1, uint32_t& r2, uint32_t& r3,
                                      uint32_t a) {
    asm volatile("ldmatrix.sync.aligned.m8n8.x4.shared.b16 {%0,%1,%2,%3}, [%4];"
                 : "=r"(r0), "=r"(r1), "=r"(r2), "=r"(r3) : "r"(a));
}
__device__ __forceinline__ void mma16816(float* c, uint32_t a0, uint32_t a1,
                                         uint32_t a2, uint32_t a3,
                                         uint32_t b0, uint32_t b1) {
    asm volatile("mma.sync.aligned.m16n8k16.row.col.f32.f16.f16.f32 "
                 "{%0,%1,%2,%3}, {%4,%5,%6,%7}, {%8,%9}, {%0,%1,%2,%3};"
                 : "+f"(c[0]), "+f"(c[1]), "+f"(c[2]), "+f"(c[3])
                 : "r"(a0), "r"(a1), "r"(a2), "r"(a3), "r"(b0), "r"(b1));
}

// compute one BK=32 stage via ldmatrix. aOff/bOff0/bOff1 are lane-resolved offsets.
__device__ __forceinline__ void compute_stage(uint32_t bufb, uint32_t aOff,
                                              uint32_t bOff0, uint32_t bOff1,
                                              float acc[4][4][4]) {
#pragma unroll
    for (int ks = 0; ks < 2; ks++) {
        uint32_t kb = ks * 32;
        uint32_t b0[4], b1[4];
        ldsm4(b0[0], b1[0], b0[1], b1[1], bufb + BPL + bOff0 + kb);
        ldsm4(b0[2], b1[2], b0[3], b1[3], bufb + BPL + bOff1 + kb);
#pragma unroll
        for (int mi = 0; mi < 4; mi++) {
            uint32_t a0, a1, a2, a3;
            ldsm4(a0, a1, a2, a3, bufb + APL + aOff + mi * (16 * ROWB) + kb);
#pragma unroll
            for (int nj = 0; nj < 4; nj++)
                mma16816(acc[mi][nj], a0, a1, a2, a3, b0[nj], b1[nj]);
        }
    }
}

// ---------------------------------------------------------------------------
__global__ void zero_init_kernel(float* __restrict__ out) {
    int i = blockIdx.x * blockDim.x + threadIdx.x;
    ((float4*)out)[i] = make_float4(0.f, 0.f, 0.f, 0.f);
    if (blockIdx.x == 0 && threadIdx.x < N_EXP) g_counts[threadIdx.x] = 0;
}

// one merged fp32->fp16 convert: x (4096 blk) | W1 (32768 blk) | W2 (32768 blk)
#define X_B4   (T_TOK * D_DIM / 4)                    // 1048576
#define W_B4   ((size_t)N_EXP * F_DIM * D_DIM / 4)    // 8388608
__global__ void f2h_all_kernel(const float* __restrict__ x,
                               const float* __restrict__ W1,
                               const float* __restrict__ W2) {
    size_t i = (size_t)blockIdx.x * blockDim.x + threadIdx.x;
    const float* s;
    __half* d;
    if (i < X_B4) { s = x; d = g_xh; }
    else if (i < X_B4 + W_B4) { s = W1; d = g_W1h; i -= X_B4; }
    else { s = W2; d = g_W2h; i -= X_B4 + W_B4; }
    float4 v = ((const float4*)s)[i];
    __half2* dp = (__half2*)d;
    dp[2 * i] = __floats2half2_rn(v.x, v.y);
    dp[2 * i + 1] = __floats2half2_rn(v.z, v.w);
}

__global__ void router_kernel(const float* __restrict__ x, const float* __restrict__ Wr) {
    int gtid = blockIdx.x * blockDim.x + threadIdx.x;
    int t = gtid >> 5, lane = gtid & 31;
    if (t >= T_TOK) return;
    const float* xr = x + (size_t)t * D_DIM;
    float xv[32];
#pragma unroll
    for (int i = 0; i < 32; i++) xv[i] = xr[lane + i * 32];
    float logit[N_EXP];
#pragma unroll
    for (int e = 0; e < N_EXP; e++) {
        const float* w = Wr + (size_t)e * D_DIM;
        float s = 0.f;
#pragma unroll
        for (int i = 0; i < 32; i++) s += xv[i] * w[lane + i * 32];
#pragma unroll
        for (int o = 16; o > 0; o >>= 1) s += __shfl_xor_sync(0xffffffffu, s, o);
        logit[e] = s;
    }
    if (lane == 0) {
        int i0 = 0; float m0v = logit[0];
#pragma unroll
        for (int e = 1; e < N_EXP; e++) if (logit[e] > m0v) { m0v = logit[e]; i0 = e; }
        int i1 = -1; float m1v = -3.0e38f;
#pragma unroll
        for (int e = 0; e < N_EXP; e++) if (e != i0 && logit[e] > m1v) { m1v = logit[e]; i1 = e; }
        float e1 = expf(m1v - m0v);
        float w0 = 1.f / (1.f + e1);
        float w1 = e1 * w0;
        g_tope[2 * t] = i0;     g_topw[2 * t] = w0;
        g_tope[2 * t + 1] = i1; g_topw[2 * t + 1] = w1;
        atomicAdd(&g_counts[i0], 1);
        atomicAdd(&g_counts[i1], 1);
    }
}

__global__ void scan_kernel() {
    int o = 0;
    for (int e = 0; e < N_EXP; e++) { g_offsets[e] = o; g_cursor[e] = o; o += g_counts[e]; }
}

__global__ void fill_kernel() {
    int t = blockIdx.x * blockDim.x + threadIdx.x;
    if (t >= T_TOK) return;
#pragma unroll
    for (int k = 0; k < 2; k++) {
        int e = g_tope[2 * t + k];
        int pos = atomicAdd(&g_cursor[e], 1);
        g_rowmap[pos] = t;
        g_roww[pos] = g_topw[2 * t + k];
    }
}

// ---------------------------------------------------------------------------
// GEMM1: H = gelu( gather(xh) @ W1h^T + b1 ). cp.async 3-stage + ldmatrix.
// producers: threads 0-127 own A row, 128-255 own B row; 64B/row/stage.
// ---------------------------------------------------------------------------
__global__ __launch_bounds__(256) void gemm1_mma(const float* __restrict__ b1) {
    int e = blockIdx.z;
    int rows = g_counts[e];
    int m0 = blockIdx.y * TM;
    if (m0 >= rows) return;
    int base = g_offsets[e];
    int n0 = blockIdx.x * TN;

    extern __shared__ char smem[];
    uint32_t sbase = smem_u32(smem);
    int tid = threadIdx.x;
    int wid = tid >> 5, lane = tid & 31;
    int wm = wid & 1, wn = wid >> 1;
    int g = lane >> 2, q2 = lane & 3;

    // producer
    int pr = tid & 127;
    bool isB = tid >= 128;
    int ar = m0 + pr; if (ar >= rows) ar = rows - 1;
    const __half* gp = isB ? (g_W1h + ((size_t)e * F_DIM + n0 + pr) * D_DIM)
                           : (g_xh + (size_t)g_rowmap[base + ar] * D_DIM);
    uint32_t sdst = sbase + (isB ? BPL : APL) + pr * ROWB;

    // ldmatrix lane offsets
    int sel = lane >> 3;
    uint32_t aOff = (uint32_t)((wm * 64 + (lane & 15)) * ROWB + (lane >> 4) * 16);
    uint32_t bOff0 = (uint32_t)((wn * 32 + 0 * 16 + (sel >> 1) * 8 + (lane & 7)) * ROWB + (sel & 1) * 16);
    uint32_t bOff1 = (uint32_t)((wn * 32 + 1 * 16 + (sel >> 1) * 8 + (lane & 7)) * ROWB + (sel & 1) * 16);

    float acc[4][4][4];
#pragma unroll
    for (int i = 0; i < 4; i++)
#pragma unroll
        for (int j = 0; j < 4; j++)
#pragma unroll
            for (int k = 0; k < 4; k++) acc[i][j][k] = 0.f;

    const int NST = D_DIM / BK;  // 32
    // prologue: stages 0, 1
#pragma unroll
    for (int s = 0; s < 2; s++) {
        const char* src = (const char*)gp + s * 64;
        uint32_t d = sdst + s * STAGE;
#pragma unroll
        for (int i = 0; i < 4; i++) cp16(d + 16 * i, src + 16 * i);
        CP_COMMIT();
    }

    int bufC = 0, bufI = 2;
    for (int kt = 0; kt < NST - 1; kt++) {
        CP_WAIT(1);
        __syncthreads();
        if (kt + 2 < NST) {
            const char* src = (const char*)gp + (kt + 2) * 64;
            uint32_t d = sdst + bufI * STAGE;
#pragma unroll
            for (int i = 0; i < 4; i++) cp16(d + 16 * i, src + 16 * i);
            CP_COMMIT();
        }
        compute_stage(sbase + bufC * STAGE, aOff, bOff0, bOff1, acc);
        bufC = (bufC + 1 == NBUF) ? 0 : bufC + 1;
        bufI = (bufI + 1 == NBUF) ? 0 : bufI + 1;
        __syncthreads();
    }
    CP_WAIT(0);
    __syncthreads();
    compute_stage(sbase + bufC * STAGE, aOff, bOff0, bOff1, acc);

    // epilogue: bias + gelu -> fp16 H
    const float* bcol = b1 + (size_t)e * F_DIM + n0 + wn * 32;
#pragma unroll
    for (int mi = 0; mi < 4; mi++) {
#pragma unroll
        for (int half_ = 0; half_ < 2; half_++) {
            int gr = m0 + wm * 64 + mi * 16 + g + half_ * 8;
            if (gr < rows) {
                __half* hrow = g_Hh + (size_t)(base + gr) * F_DIM + n0 + wn * 32;
#pragma unroll
                for (int nj = 0; nj < 4; nj++) {
                    int n = nj * 8 + q2 * 2;
                    float v0 = acc[mi][nj][half_ * 2 + 0] + bcol[n];
                    float v1 = acc[mi][nj][half_ * 2 + 1] + bcol[n + 1];
                    float g0 = 0.5f * v0 * (1.0f + erff(v0 * 0.7071067811865475f));
                    float g1 = 0.5f * v1 * (1.0f + erff(v1 * 0.7071067811865475f));
                    *(__half2*)(hrow + n) = __floats2half2_rn(g0, g1);
                }
            }
        }
    }
}

// ---------------------------------------------------------------------------
// GEMM2: Y = Hh @ W2h^T + b2; out[tok] += w * Y (2-way atomic: deterministic)
// ---------------------------------------------------------------------------
__global__ __launch_bounds__(256) void gemm2_mma(const float* __restrict__ b2,
                                                 float* __restrict__ out) {
    int e = blockIdx.z;
    int rows = g_counts[e];
    int m0 = blockIdx.y * TM;
    if (m0 >= rows) return;
    int base = g_offsets[e];
    int n0 = blockIdx.x * TN;   // over D_DIM

    extern __shared__ char smem[];
    uint32_t sbase = smem_u32(smem);
    int tid = threadIdx.x;
    int wid = tid >> 5, lane = tid & 31;
    int wm = wid & 1, wn = wid >> 1;
    int g = lane >> 2, q2 = lane & 3;

    int pr = tid & 127;
    bool isB = tid >= 128;
    int ar = m0 + pr; if (ar >= rows) ar = rows - 1;
    const __half* gp = isB ? (g_W2h + ((size_t)e * D_DIM + n0 + pr) * F_DIM)
                           : (g_Hh + (size_t)(base + ar) * F_DIM);
    uint32_t sdst = sbase + (isB ? BPL : APL) + pr * ROWB;

    int sel = lane >> 3;
    uint32_t aOff = (uint32_t)((wm * 64 + (lane & 15)) * ROWB + (lane >> 4) * 16);
    uint32_t bOff0 = (uint32_t)((wn * 32 + 0 * 16 + (sel >> 1) * 8 + (lane & 7)) * ROWB + (sel & 1) * 16);
    uint32_t bOff1 = (uint32_t)((wn * 32 + 1 * 16 + (sel >> 1) * 8 + (lane & 7)) * ROWB + (sel & 1) * 16);

    float acc[4][4][4];
#pragma unroll
    for (int i = 0; i < 4; i++)
#pragma unroll
        for (int j = 0; j < 4; j++)
#pragma unroll
            for (int k = 0; k < 4; k++) acc[i][j][k] = 0.f;

    const int NST = F_DIM / BK;  // 128
#pragma unroll
    for (int s = 0; s < 2; s++) {
        const char* src = (const char*)gp + s * 64;
        uint32_t d = sdst + s * STAGE;
#pragma unroll
        for (int i = 0; i < 4; i++) cp16(d + 16 * i, src + 16 * i);
        CP_COMMIT();
    }

    int bufC = 0, bufI = 2;
    for (int kt = 0; kt < NST - 1; kt++) {
        CP_WAIT(1);
        __syncthreads();
        if (kt + 2 < NST) {
            const char* src = (const char*)gp + (kt + 2) * 64;
            uint32_t d = sdst + bufI * STAGE;
#pragma unroll
            for (int i = 0; i < 4; i++) cp16(d + 16 * i, src + 16 * i);
            CP_COMMIT();
        }
        compute_stage(sbase + bufC * STAGE, aOff, bOff0, bOff1, acc);
        bufC = (bufC + 1 == NBUF) ? 0 : bufC + 1;
        bufI = (bufI + 1 == NBUF) ? 0 : bufI + 1;
        __syncthreads();
    }
    CP_WAIT(0);
    __syncthreads();
    compute_stage(sbase + bufC * STAGE, aOff, bOff0, bOff1, acc);

    const float* bcol = b2 + (size_t)e * D_DIM + n0 + wn * 32;
#pragma unroll
    for (int mi = 0; mi < 4; mi++) {
#pragma unroll
        for (int half_ = 0; half_ < 2; half_++) {
            int gr = m0 + wm * 64 + mi * 16 + g + half_ * 8;
            if (gr < rows) {
                int tok = g_rowmap[base + gr];
                float w = g_roww[base + gr];
                float* op = out + (size_t)tok * D_DIM + n0 + wn * 32;
#pragma unroll
                for (int nj = 0; nj < 4; nj++) {
                    int n = nj * 8 + q2 * 2;
                    float v0 = acc[mi][nj][half_ * 2 + 0] + bcol[n];
                    float v1 = acc[mi][nj][half_ * 2 + 1] + bcol[n + 1];
                    atomicAdd(&op[n], w * v0);
                    atomicAdd(&op[n + 1], w * v1);
                }
            }
        }
    }
}

// ---------------------------------------------------------------------------
extern "C" void kernel_launch(void* const* d_in, const int* in_sizes, int n_in,
                              void* d_out, int out_size) {
    const float* x  = (const float*)d_in[0];
    const float* Wr = (const float*)d_in[1];
    const float* W1 = (const float*)d_in[2];
    const float* b1 = (const float*)d_in[3];
    const float* W2 = (const float*)d_in[4];
    const float* b2 = (const float*)d_in[5];
    float* out = (float*)d_out;

    cudaFuncSetAttribute(gemm1_mma, cudaFuncAttributeMaxDynamicSharedMemorySize, DSMEM);
    cudaFuncSetAttribute(gemm2_mma, cudaFuncAttributeMaxDynamicSharedMemorySize, DSMEM);

    // launch order puts gemm1_mma at index 5 so ncu -s 5 profiles it
    zero_init_kernel<<<4096, 256>>>(out);
    f2h_all_kernel<<<(unsigned)((X_B4 + 2 * W_B4) / 256), 256>>>(x, W1, W2);
    router_kernel<<<(T_TOK * 32) / 256, 256>>>(x, Wr);
    scan_kernel<<<1, 1>>>();
    fill_kernel<<<T_TOK / 256, 256>>>();
    gemm1_mma<<<dim3(F_DIM / TN, T_TOK / TM, N_EXP), 256, DSMEM>>>(b1);
    gemm2_mma<<<dim3(D_DIM / TN, T_TOK / TM, N_EXP), 256, DSMEM>>>(b2, out);
}

// round 11
// speedup vs baseline: 4.0909x; 1.1028x over previous
#include <cuda_runtime.h>
#include <cuda_fp16.h>
#include <math.h>
#include <stdint.h>

#define T_TOK 4096
#define D_DIM 1024
#define F_DIM 4096
#define N_EXP 8
#define TOTAL_ROWS (T_TOK * 2)

#define TM 128
#define TN 128
#define BK 32

// smem: 2 fp16 planes per stage, 80-byte row stride (64B data + 16B pad)
#define ROWB 80
#define APL 0
#define BPL (128 * ROWB)            // 10240
#define STAGE (2 * 128 * ROWB)      // 20480
#define NBUF 4
#define DSMEM (NBUF * STAGE)        // 81920  (2 CTAs = 160KB <= 228KB/SM)

// ---- scratch (device globals: no allocations allowed) ----
__device__ __half g_Hh[(size_t)TOTAL_ROWS * F_DIM];
__device__ __half g_W1h[(size_t)N_EXP * F_DIM * D_DIM];
__device__ __half g_W2h[(size_t)N_EXP * D_DIM * F_DIM];
__device__ __half g_xh[(size_t)T_TOK * D_DIM];
__device__ int   g_rowmap[TOTAL_ROWS];
__device__ float g_roww[TOTAL_ROWS];
__device__ int   g_counts[N_EXP];
__device__ int   g_offsets[N_EXP];
__device__ int   g_tope[T_TOK * 2];
__device__ float g_topw[T_TOK * 2];

// ---------------- PTX helpers ----------------
__device__ __forceinline__ uint32_t smem_u32(const void* p) {
    uint32_t a;
    asm("{ .reg .u64 t; cvta.to.shared.u64 t, %1; cvt.u32.u64 %0, t; }" : "=r"(a) : "l"(p));
    return a;
}
__device__ __forceinline__ void cp16(uint32_t dst, const void* src) {
    asm volatile("cp.async.cg.shared.global [%0], [%1], 16;" :: "r"(dst), "l"(src));
}
#define CP_COMMIT() asm volatile("cp.async.commit_group;" ::: "memory")
#define CP_WAIT(n)  asm volatile("cp.async.wait_group %0;" :: "n"(n) : "memory")
__device__ __forceinline__ void ldsm4(uint32_t& r0, uint32_t& r1, uint32_t& r2, uint32_t& r3,
                                      uint32_t a) {
    asm volatile("ldmatrix.sync.aligned.m8n8.x4.shared.b16 {%0,%1,%2,%3}, [%4];"
                 : "=r"(r0), "=r"(r1), "=r"(r2), "=r"(r3) : "r"(a));
}
__device__ __forceinline__ void mma16816(float* c, uint32_t a0, uint32_t a1,
                                         uint32_t a2, uint32_t a3,
                                         uint32_t b0, uint32_t b1) {
    asm volatile("mma.sync.aligned.m16n8k16.row.col.f32.f16.f16.f32 "
                 "{%0,%1,%2,%3}, {%4,%5,%6,%7}, {%8,%9}, {%0,%1,%2,%3};"
                 : "+f"(c[0]), "+f"(c[1]), "+f"(c[2]), "+f"(c[3])
                 : "r"(a0), "r"(a1), "r"(a2), "r"(a3), "r"(b0), "r"(b1));
}

// compute one BK=32 stage via ldmatrix
__device__ __forceinline__ void compute_stage(uint32_t bufb, uint32_t aOff,
                                              uint32_t bOff0, uint32_t bOff1,
                                              float acc[4][4][4]) {
#pragma unroll
    for (int ks = 0; ks < 2; ks++) {
        uint32_t kb = ks * 32;
        uint32_t b0[4], b1[4];
        ldsm4(b0[0], b1[0], b0[1], b1[1], bufb + BPL + bOff0 + kb);
        ldsm4(b0[2], b1[2], b0[3], b1[3], bufb + BPL + bOff1 + kb);
#pragma unroll
        for (int mi = 0; mi < 4; mi++) {
            uint32_t a0, a1, a2, a3;
            ldsm4(a0, a1, a2, a3, bufb + APL + aOff + mi * (16 * ROWB) + kb);
#pragma unroll
            for (int nj = 0; nj < 4; nj++)
                mma16816(acc[mi][nj], a0, a1, a2, a3, b0[nj], b1[nj]);
        }
    }
}

// ---------------------------------------------------------------------------
// launch 0: fp32->fp16 converts for x|W1|W2, plus zero(out) and counts reset
#define X_B4   ((size_t)(T_TOK * D_DIM / 4))          // 1048576 == out float4 count
#define W_B4   ((size_t)N_EXP * F_DIM * D_DIM / 4)    // 8388608
__global__ void f2h_zero_kernel(const float* __restrict__ x,
                                const float* __restrict__ W1,
                                const float* __restrict__ W2,
                                float* __restrict__ out) {
    size_t i = (size_t)blockIdx.x * blockDim.x + threadIdx.x;
    if (i < X_B4) ((float4*)out)[i] = make_float4(0.f, 0.f, 0.f, 0.f);
    if (i < 8) g_counts[i] = 0;
    const float* s;
    __half* d;
    size_t j = i;
    if (j < X_B4) { s = x; d = g_xh; }
    else if (j < X_B4 + W_B4) { s = W1; d = g_W1h; j -= X_B4; }
    else { s = W2; d = g_W2h; j -= X_B4 + W_B4; }
    float4 v = ((const float4*)s)[j];
    __half2* dp = (__half2*)d;
    dp[2 * j] = __floats2half2_rn(v.x, v.y);
    dp[2 * j + 1] = __floats2half2_rn(v.z, v.w);
}

// launch 1: router
__global__ void router_kernel(const float* __restrict__ x, const float* __restrict__ Wr) {
    int gtid = blockIdx.x * blockDim.x + threadIdx.x;
    int t = gtid >> 5, lane = gtid & 31;
    if (t >= T_TOK) return;
    const float* xr = x + (size_t)t * D_DIM;
    float xv[32];
#pragma unroll
    for (int i = 0; i < 32; i++) xv[i] = xr[lane + i * 32];
    float logit[N_EXP];
#pragma unroll
    for (int e = 0; e < N_EXP; e++) {
        const float* w = Wr + (size_t)e * D_DIM;
        float s = 0.f;
#pragma unroll
        for (int i = 0; i < 32; i++) s += xv[i] * w[lane + i * 32];
#pragma unroll
        for (int o = 16; o > 0; o >>= 1) s += __shfl_xor_sync(0xffffffffu, s, o);
        logit[e] = s;
    }
    if (lane == 0) {
        int i0 = 0; float m0v = logit[0];
#pragma unroll
        for (int e = 1; e < N_EXP; e++) if (logit[e] > m0v) { m0v = logit[e]; i0 = e; }
        int i1 = -1; float m1v = -3.0e38f;
#pragma unroll
        for (int e = 0; e < N_EXP; e++) if (e != i0 && logit[e] > m1v) { m1v = logit[e]; i1 = e; }
        float e1 = expf(m1v - m0v);
        float w0 = 1.f / (1.f + e1);
        float w1 = e1 * w0;
        g_tope[2 * t] = i0;     g_topw[2 * t] = w0;
        g_tope[2 * t + 1] = i1; g_topw[2 * t + 1] = w1;
        atomicAdd(&g_counts[i0], 1);
        atomicAdd(&g_counts[i1], 1);
    }
}

// launch 2: scan + fill merged (single block)
__global__ void scanfill_kernel() {
    __shared__ int scur[N_EXP];
    int tid = threadIdx.x;
    if (tid == 0) {
        int o = 0;
        for (int e = 0; e < N_EXP; e++) { g_offsets[e] = o; scur[e] = o; o += g_counts[e]; }
    }
    __syncthreads();
    for (int t = tid; t < T_TOK; t += 256) {
#pragma unroll
        for (int k = 0; k < 2; k++) {
            int e = g_tope[2 * t + k];
            int pos = atomicAdd(&scur[e], 1);
            g_rowmap[pos] = t;
            g_roww[pos] = g_topw[2 * t + k];
        }
    }
}

// ---------------------------------------------------------------------------
// launch 3: GEMM1: H = gelu( gather(xh) @ W1h^T + b1 )
// cp.async 4-buffer pipeline, 1 sync/stage, ldmatrix, fp16 MMA fp32 accum
// ---------------------------------------------------------------------------
__global__ __launch_bounds__(256, 2) void gemm1_mma(const float* __restrict__ b1) {
    int e = blockIdx.z;
    int rows = g_counts[e];
    int m0 = blockIdx.y * TM;
    if (m0 >= rows) return;
    int base = g_offsets[e];
    int n0 = blockIdx.x * TN;

    extern __shared__ char smem[];
    uint32_t sbase = smem_u32(smem);
    int tid = threadIdx.x;
    int wid = tid >> 5, lane = tid & 31;
    int wm = wid & 1, wn = wid >> 1;
    int g = lane >> 2, q2 = lane & 3;

    int pr = tid & 127;
    bool isB = tid >= 128;
    int ar = m0 + pr; if (ar >= rows) ar = rows - 1;
    const __half* gp = isB ? (g_W1h + ((size_t)e * F_DIM + n0 + pr) * D_DIM)
                           : (g_xh + (size_t)g_rowmap[base + ar] * D_DIM);
    uint32_t sdst = sbase + (isB ? BPL : APL) + pr * ROWB;

    int sel = lane >> 3;
    uint32_t aOff = (uint32_t)((wm * 64 + (lane & 15)) * ROWB + (lane >> 4) * 16);
    uint32_t bOff0 = (uint32_t)((wn * 32 + (sel >> 1) * 8 + (lane & 7)) * ROWB + (sel & 1) * 16);
    uint32_t bOff1 = (uint32_t)((wn * 32 + 16 + (sel >> 1) * 8 + (lane & 7)) * ROWB + (sel & 1) * 16);

    float acc[4][4][4];
#pragma unroll
    for (int i = 0; i < 4; i++)
#pragma unroll
        for (int j = 0; j < 4; j++)
#pragma unroll
            for (int k = 0; k < 4; k++) acc[i][j][k] = 0.f;

    const int NST = D_DIM / BK;  // 32
#pragma unroll
    for (int s = 0; s < 3; s++) {
        const char* src = (const char*)gp + s * 64;
        uint32_t d = sdst + s * STAGE;
#pragma unroll
        for (int i = 0; i < 4; i++) cp16(d + 16 * i, src + 16 * i);
        CP_COMMIT();
    }

    for (int kt = 0; kt < NST; kt++) {
        CP_WAIT(2);
        __syncthreads();
        if (kt + 3 < NST) {
            const char* src = (const char*)gp + (kt + 3) * 64;
            uint32_t d = sdst + ((kt + 3) & 3) * STAGE;
#pragma unroll
            for (int i = 0; i < 4; i++) cp16(d + 16 * i, src + 16 * i);
        }
        CP_COMMIT();   // always commit (possibly empty) to keep wait_group(2) exact
        compute_stage(sbase + (kt & 3) * STAGE, aOff, bOff0, bOff1, acc);
    }

    // epilogue: bias + gelu -> fp16 H
    const float* bcol = b1 + (size_t)e * F_DIM + n0 + wn * 32;
#pragma unroll
    for (int mi = 0; mi < 4; mi++) {
#pragma unroll
        for (int half_ = 0; half_ < 2; half_++) {
            int gr = m0 + wm * 64 + mi * 16 + g + half_ * 8;
            if (gr < rows) {
                __half* hrow = g_Hh + (size_t)(base + gr) * F_DIM + n0 + wn * 32;
#pragma unroll
                for (int nj = 0; nj < 4; nj++) {
                    int n = nj * 8 + q2 * 2;
                    float v0 = acc[mi][nj][half_ * 2 + 0] + bcol[n];
                    float v1 = acc[mi][nj][half_ * 2 + 1] + bcol[n + 1];
                    float g0 = 0.5f * v0 * (1.0f + erff(v0 * 0.7071067811865475f));
                    float g1 = 0.5f * v1 * (1.0f + erff(v1 * 0.7071067811865475f));
                    *(__half2*)(hrow + n) = __floats2half2_rn(g0, g1);
                }
            }
        }
    }
}

// ---------------------------------------------------------------------------
// launch 4: GEMM2: Y = Hh @ W2h^T + b2; out[tok] += w * Y (2-way atomic)
// ---------------------------------------------------------------------------
__global__ __launch_bounds__(256, 2) void gemm2_mma(const float* __restrict__ b2,
                                                    float* __restrict__ out) {
    int e = blockIdx.z;
    int rows = g_counts[e];
    int m0 = blockIdx.y * TM;
    if (m0 >= rows) return;
    int base = g_offsets[e];
    int n0 = blockIdx.x * TN;   // over D_DIM

    extern __shared__ char smem[];
    uint32_t sbase = smem_u32(smem);
    int tid = threadIdx.x;
    int wid = tid >> 5, lane = tid & 31;
    int wm = wid & 1, wn = wid >> 1;
    int g = lane >> 2, q2 = lane & 3;

    int pr = tid & 127;
    bool isB = tid >= 128;
    int ar = m0 + pr; if (ar >= rows) ar = rows - 1;
    const __half* gp = isB ? (g_W2h + ((size_t)e * D_DIM + n0 + pr) * F_DIM)
                           : (g_Hh + (size_t)(base + ar) * F_DIM);
    uint32_t sdst = sbase + (isB ? BPL : APL) + pr * ROWB;

    int sel = lane >> 3;
    uint32_t aOff = (uint32_t)((wm * 64 + (lane & 15)) * ROWB + (lane >> 4) * 16);
    uint32_t bOff0 = (uint32_t)((wn * 32 + (sel >> 1) * 8 + (lane & 7)) * ROWB + (sel & 1) * 16);
    uint32_t bOff1 = (uint32_t)((wn * 32 + 16 + (sel >> 1) * 8 + (lane & 7)) * ROWB + (sel & 1) * 16);

    float acc[4][4][4];
#pragma unroll
    for (int i = 0; i < 4; i++)
#pragma unroll
        for (int j = 0; j < 4; j++)
#pragma unroll
            for (int k = 0; k < 4; k++) acc[i][j][k] = 0.f;

    const int NST = F_DIM / BK;  // 128
#pragma unroll
    for (int s = 0; s < 3; s++) {
        const char* src = (const char*)gp + s * 64;
        uint32_t d = sdst + s * STAGE;
#pragma unroll
        for (int i = 0; i < 4; i++) cp16(d + 16 * i, src + 16 * i);
        CP_COMMIT();
    }

    for (int kt = 0; kt < NST; kt++) {
        CP_WAIT(2);
        __syncthreads();
        if (kt + 3 < NST) {
            const char* src = (const char*)gp + (kt + 3) * 64;
            uint32_t d = sdst + ((kt + 3) & 3) * STAGE;
#pragma unroll
            for (int i = 0; i < 4; i++) cp16(d + 16 * i, src + 16 * i);
        }
        CP_COMMIT();
        compute_stage(sbase + (kt & 3) * STAGE, aOff, bOff0, bOff1, acc);
    }

    const float* bcol = b2 + (size_t)e * D_DIM + n0 + wn * 32;
#pragma unroll
    for (int mi = 0; mi < 4; mi++) {
#pragma unroll
        for (int half_ = 0; half_ < 2; half_++) {
            int gr = m0 + wm * 64 + mi * 16 + g + half_ * 8;
            if (gr < rows) {
                int tok = g_rowmap[base + gr];
                float w = g_roww[base + gr];
                float* op = out + (size_t)tok * D_DIM + n0 + wn * 32;
#pragma unroll
                for (int nj = 0; nj < 4; nj++) {
                    int n = nj * 8 + q2 * 2;
                    float v0 = acc[mi][nj][half_ * 2 + 0] + bcol[n];
                    float v1 = acc[mi][nj][half_ * 2 + 1] + bcol[n + 1];
                    atomicAdd(&op[n], w * v0);
                    atomicAdd(&op[n + 1], w * v1);
                }
            }
        }
    }
}

// ---------------------------------------------------------------------------
extern "C" void kernel_launch(void* const* d_in, const int* in_sizes, int n_in,
                              void* d_out, int out_size) {
    const float* x  = (const float*)d_in[0];
    const float* Wr = (const float*)d_in[1];
    const float* W1 = (const float*)d_in[2];
    const float* b1 = (const float*)d_in[3];
    const float* W2 = (const float*)d_in[4];
    const float* b2 = (const float*)d_in[5];
    float* out = (float*)d_out;

    cudaFuncSetAttribute(gemm1_mma, cudaFuncAttributeMaxDynamicSharedMemorySize, DSMEM);
    cudaFuncSetAttribute(gemm2_mma, cudaFuncAttributeMaxDynamicSharedMemorySize, DSMEM);

    // launch indices: 0 f2h_zero, 1 router, 2 scanfill, 3 gemm1 (ncu target), 4 gemm2
    f2h_zero_kernel<<<(unsigned)((X_B4 + 2 * W_B4) / 256), 256>>>(x, W1, W2, out);
    router_kernel<<<(T_TOK * 32) / 256, 256>>>(x, Wr);
    scanfill_kernel<<<1, 256>>>();
    gemm1_mma<<<dim3(F_DIM / TN, T_TOK / TM, N_EXP), 256, DSMEM>>>(b1);
    gemm2_mma<<<dim3(D_DIM / TN, T_TOK / TM, N_EXP), 256, DSMEM>>>(b2, out);
}